// round 15
// baseline (speedup 1.0000x reference)
#include <cuda_runtime.h>
#include <math.h>

// Problem shapes (fixed for MultiLoss_87668872446687)
#define BB 2
#define AA 16384
#define GG 24
#define CC 8
#define TPB 256
#define AB 64                       // anchors per block (4 threads per anchor)
#define GPT 6                       // gts per thread (24/4)
#define NBLK (AA / AB)              // 256 blocks per image
#define NBLK_TOT (BB * NBLK)        // 512
#define QCAP (AB * GG)              // 1536 = hard maximum

// ---------------- scratch (device globals; no allocations) ----------------
__device__ unsigned long long g_gtkey[BB * GG];
__device__ float  g_part[NBLK_TOT * 4];
__device__ float4 g_delta[BB * AA];
__device__ unsigned g_done;

// ---------------- helpers ----------------
__device__ __forceinline__ float smooth_l1(float d) {
    const float beta = 1.0f / 9.0f;
    d = fabsf(d);
    return (d < beta) ? (0.5f * d * d / beta) : (d - 0.5f * beta);
}

__device__ __forceinline__ float balanced_l1(float d) {
    const float bb = 5.0496474644129465f;  // e^(0.9/0.5) - 1
    const float al = 0.5f, ga = 0.9f, beta = 0.5f;
    d = fabsf(d);
    if (d < beta)
        return al / bb * (bb * d + 1.0f) * __logf(bb * d / beta + 1.0f) - al * d;
    return ga * d + ga / bb - al * beta;
}

__device__ __forceinline__ float focal_neg(float p) {
    p = fminf(fmaxf(p, 1e-4f), 1.0f - 1e-4f);
    return 0.75f * p * p * (-__logf(1.0f - p + 1e-6f));
}
__device__ __forceinline__ float focal_pos(float p) {
    p = fminf(fmaxf(p, 1e-4f), 1.0f - 1e-4f);
    float q = 1.0f - p;
    return 0.25f * q * q * (-__logf(p + 1e-6f));
}

// value-based: reg row r0..r4 and lmk row k0..k3 already in registers
__device__ __forceinline__ void pos_losses_v(
        float acx, float acy, float aw, float ah, float ath,
        const float* gp, const float* lp,
        float r0, float r1, float r2, float r3, float r4,
        float k0, float k1, float k2, float k3,
        float& regsum, float& lmksum) {
    float ew = fmaxf(aw, 1.0f), eh = fmaxf(ah, 1.0f);
    float gw = fmaxf(gp[2], 1.0f), gh = fmaxf(gp[3], 1.0f);
    float ta = __tanf(ath);
    float dx = 10.0f * (gp[0] - acx) / ew;
    float dy = 10.0f * (gp[1] - acy) / eh;
    float dw = 5.0f * __logf(gw / ew);
    float dh = 5.0f * __logf(gh / eh);
    float dt = 15.0f * (__tanf(gp[4]) - ta);

    float tg = r4 / 15.0f + ta;
    if (fabsf(tg) < 1e-4f) tg = (tg < 0.0f) ? -1e-4f : 1e-4f;
    float t22 = 15.0f * (-1.0f / tg - ta);

    float l1 = smooth_l1(dx - r0), l2 = smooth_l1(dy - r1);
    float l3 = smooth_l1(dw - r2), l4 = smooth_l1(dh - r3);
    float l5 = smooth_l1(dw - r3), l6 = smooth_l1(dh - r2);
    float l7 = smooth_l1(dt - r4), l8 = smooth_l1(dt - t22);
    regsum = fminf(l1 + l2 + l3 + l4 + l7, l1 + l2 + l5 + l6 + l8);

    float t0 = 10.0f * (lp[0] - acx) / ew;
    float t1_ = 10.0f * (lp[1] - acy) / eh;
    float t2 = 10.0f * (lp[2] - acx) / ew;
    float t3 = 10.0f * (lp[3] - acy) / eh;
    lmksum = balanced_l1(k0 - t0) + balanced_l1(k1 - t1_) +
             balanced_l1(k2 - t2) + balanced_l1(k3 - t3);
}

// ---------------- fused kernel ----------------
__global__ void __launch_bounds__(TPB) k_main(
        const float* __restrict__ anchors,
        const float* __restrict__ ann,
        const float* __restrict__ cls,
        const float* __restrict__ reg,
        const float* __restrict__ lmk,
        const float* __restrict__ ls,
        float* __restrict__ out) {
    // gt caches
    __shared__ float s_gx0[GG], s_gy0[GG], s_gx1[GG], s_gy1[GG], s_areaG[GG];
    __shared__ float s_gax[GG][4], s_gay[GG][4];
    __shared__ float s_gdx[GG][4], s_gdy[GG][4];
    __shared__ float s_gwh[GG];
    __shared__ float s_gdat[GG][6];
    __shared__ float s_lsd[GG][4];
    __shared__ int   s_valid[GG];
    __shared__ int   s_anyv;
    __shared__ unsigned long long s_gtkey[GG];
    // per-anchor (AB = 64)
    __shared__ unsigned long long s_akey[AB];
    __shared__ float s_corn[8 * AB];
    __shared__ float s_cwh[AB];
    __shared__ float s_sq[5 * AB];
    __shared__ int   s_winner[AB];
    // pair queue
    __shared__ unsigned short s_q[QCAP];
    __shared__ int s_qn;
    __shared__ int s_last;
    // clip scratch: buffer A = slots 0..6, buffer B = slots 7..12
    __shared__ float s_clip[26 * TPB];
    __shared__ float s_wred[8 * 4];
    // fixer state
    __shared__ unsigned long long f_key[BB * GG];
    __shared__ float f_lab[BB * GG];
    __shared__ float f_dc[BB * GG], f_dr[BB * GG], f_dl[BB * GG], f_dn[BB * GG];
    __shared__ int   f_arg[BB * GG], f_forced[BB * GG];
    __shared__ float f_w[8 * 4];
    __shared__ float f_img[BB][3];

    const int b = blockIdx.y;
    const int tid = threadIdx.x;
    const int al = tid & (AB - 1);       // anchor within block
    const int part = tid >> 6;           // 0..3: which 6 gts this thread covers
    const int a = blockIdx.x * AB + al;  // global anchor within image
    const long idx = (long)b * AA + a;

    if (tid == 0) s_qn = 0;
    if (tid < AB) s_winner[al] = 0;
    if (tid < GG) {
        const float* gp = ann + (b * GG + tid) * 6;
        float gx = gp[0], gy = gp[1], gw = gp[2], gh = gp[3], gt = gp[4];
        s_gdat[tid][0] = gx; s_gdat[tid][1] = gy; s_gdat[tid][2] = gw;
        s_gdat[tid][3] = gh; s_gdat[tid][4] = gt; s_gdat[tid][5] = gp[5];
        s_valid[tid] = (gp[5] != -1.0f);
        s_gwh[tid] = gw * gh;
        float gs2 = 0.5f * fmaxf(gw, gh);
        float x0 = gx - gs2, y0 = gy - gs2, x1 = gx + gs2, y1 = gy + gs2;
        s_gx0[tid] = x0; s_gy0[tid] = y0; s_gx1[tid] = x1; s_gy1[tid] = y1;
        s_areaG[tid] = (x1 - x0) * (y1 - y0);
        float c = cosf(gt), s = sinf(gt);
        float hw = 0.5f * gw, hh = 0.5f * gh;
        float cx0 = gx - hw * c + hh * s, cy0 = gy - hw * s - hh * c;
        float cx1 = gx + hw * c + hh * s, cy1 = gy + hw * s - hh * c;
        float cx2 = gx + hw * c - hh * s, cy2 = gy + hw * s + hh * c;
        float cx3 = gx - hw * c - hh * s, cy3 = gy - hw * s + hh * c;
        s_gax[tid][0] = cx0; s_gay[tid][0] = cy0;
        s_gdx[tid][0] = cx1 - cx0; s_gdy[tid][0] = cy1 - cy0;
        s_gax[tid][1] = cx1; s_gay[tid][1] = cy1;
        s_gdx[tid][1] = cx2 - cx1; s_gdy[tid][1] = cy2 - cy1;
        s_gax[tid][2] = cx2; s_gay[tid][2] = cy2;
        s_gdx[tid][2] = cx3 - cx2; s_gdy[tid][2] = cy3 - cy2;
        s_gax[tid][3] = cx3; s_gay[tid][3] = cy3;
        s_gdx[tid][3] = cx0 - cx3; s_gdy[tid][3] = cy0 - cy3;
        s_gtkey[tid] = 0ull;
        const float* lq = ls + (b * GG + tid) * 4;
        s_lsd[tid][0] = lq[0]; s_lsd[tid][1] = lq[1];
        s_lsd[tid][2] = lq[2]; s_lsd[tid][3] = lq[3];
    }

    // primary thread per anchor; prefetch cls/reg/lmk early (phase C inputs)
    float ax = 0, ay = 0, aw = 0, ah = 0, at = 0;
    float4 pc0 = make_float4(0.f, 0.f, 0.f, 0.f);
    float4 pc1 = make_float4(0.f, 0.f, 0.f, 0.f);
    float pr0 = 0.f, pr1 = 0.f, pr2 = 0.f, pr3 = 0.f, pr4 = 0.f;
    float4 pk = make_float4(0.f, 0.f, 0.f, 0.f);
    if (tid < AB) {
        const float4* cv = (const float4*)(cls + idx * CC);
        pc0 = cv[0]; pc1 = cv[1];
        const float* rp = reg + idx * 5;
        pr0 = rp[0]; pr1 = rp[1]; pr2 = rp[2]; pr3 = rp[3]; pr4 = rp[4];
        pk = ((const float4*)lmk)[idx];
        const float* apt = anchors + idx * 5;
        ax = apt[0]; ay = apt[1]; aw = apt[2]; ah = apt[3]; at = apt[4];
        float c = cosf(at), s = sinf(at);
        float hw = 0.5f * aw, hh = 0.5f * ah;
        s_corn[0 * AB + al] = ax - hw * c + hh * s;
        s_corn[1 * AB + al] = ay - hw * s - hh * c;
        s_corn[2 * AB + al] = ax + hw * c + hh * s;
        s_corn[3 * AB + al] = ay + hw * s - hh * c;
        s_corn[4 * AB + al] = ax + hw * c - hh * s;
        s_corn[5 * AB + al] = ay + hw * s + hh * c;
        s_corn[6 * AB + al] = ax - hw * c - hh * s;
        s_corn[7 * AB + al] = ay - hw * s + hh * c;
        s_cwh[al] = aw * ah;
        float as2 = 0.5f * fmaxf(aw, ah);
        float x0 = ax - as2, y0 = ay - as2, x1 = ax + as2, y1 = ay + as2;
        s_sq[0 * AB + al] = x0; s_sq[1 * AB + al] = y0;
        s_sq[2 * AB + al] = x1; s_sq[3 * AB + al] = y1;
        s_sq[4 * AB + al] = (x1 - x0) * (y1 - y0);
        s_akey[al] = 0ull;
    }
    __syncthreads();

    if (tid == 0) {
        int v = 0;
        #pragma unroll
        for (int g = 0; g < GG; g++) v |= s_valid[g];
        s_anyv = v;
    }

    // clip: buffers A (slots 0..6), B (slots 7..12); edge3 fused with area
    #define SXc(i) s_clip[(i) * TPB + tid]
    #define SYc(i) s_clip[(13 + (i)) * TPB + tid]
    auto do_clip = [&](int a2, int g) -> float {
        float v0x = s_corn[0 * AB + a2], v0y = s_corn[1 * AB + a2];
        float v1x = s_corn[2 * AB + a2], v1y = s_corn[3 * AB + a2];
        float v2x = s_corn[4 * AB + a2], v2y = s_corn[5 * AB + a2];
        float v3x = s_corn[6 * AB + a2], v3y = s_corn[7 * AB + a2];

        // edge 0: input = rect corners (registers) -> buffer A
        float aex = s_gax[g][0], aey = s_gay[g][0];
        float dx = s_gdx[g][0], dy = s_gdy[g][0];
        float sc0 = dx * (v0y - aey) - dy * (v0x - aex);
        float sc1 = dx * (v1y - aey) - dy * (v1x - aex);
        float sc2 = dx * (v2y - aey) - dy * (v2x - aex);
        float sc3 = dx * (v3y - aey) - dy * (v3x - aex);
        int m = 0;
        #define EMIT0(cx, cy, nx, ny, sc, sn)                          \
            do {                                                       \
                bool ic = ((sc) >= 0.0f), in2 = ((sn) >= 0.0f);        \
                if (ic) { SXc(m) = (cx); SYc(m) = (cy); m++; }         \
                if (ic != in2) {                                       \
                    float t = (sc) / ((sc) - (sn));                    \
                    SXc(m) = (cx) + t * ((nx) - (cx));                 \
                    SYc(m) = (cy) + t * ((ny) - (cy));                 \
                    m++;                                               \
                }                                                      \
            } while (0)
        EMIT0(v0x, v0y, v1x, v1y, sc0, sc1);
        EMIT0(v1x, v1y, v2x, v2y, sc1, sc2);
        EMIT0(v2x, v2y, v3x, v3y, sc2, sc3);
        EMIT0(v3x, v3y, v0x, v0y, sc3, sc0);
        #undef EMIT0

        int n = m;
        // edges 1 (A->B) and 2 (B->A)
        #pragma unroll
        for (int e = 1; e <= 2; e++) {
            if (n == 0) break;
            int rb = (e == 1) ? 0 : 7;
            int wb = (e == 1) ? 7 : 0;
            aex = s_gax[g][e]; aey = s_gay[g][e];
            dx = s_gdx[g][e];  dy = s_gdy[g][e];
            m = 0;
            float fx = SXc(rb), fy = SYc(rb);
            float cx = fx, cy = fy;
            float sc = dx * (cy - aey) - dy * (cx - aex);
            float sf = sc;
            for (int i = 0; i < n; i++) {
                float nx, ny, sn;
                if (i + 1 == n) { nx = fx; ny = fy; sn = sf; }
                else {
                    nx = SXc(rb + i + 1); ny = SYc(rb + i + 1);
                    sn = dx * (ny - aey) - dy * (nx - aex);
                }
                bool ic = (sc >= 0.0f), in2 = (sn >= 0.0f);
                if (ic) { SXc(wb + m) = cx; SYc(wb + m) = cy; m++; }
                if (ic != in2) {
                    float t = sc / (sc - sn);
                    SXc(wb + m) = cx + t * (nx - cx);
                    SYc(wb + m) = cy + t * (ny - cy);
                    m++;
                }
                cx = nx; cy = ny; sc = sn;
            }
            n = m;
        }

        // edge 3 (reads A) fused with shoelace area (bit-identical order)
        float cr = 0.0f;
        if (n) {
            aex = s_gax[g][3]; aey = s_gay[g][3];
            dx = s_gdx[g][3];  dy = s_gdy[g][3];
            float fox = 0.0f, foy = 0.0f, pvx = 0.0f, pvy = 0.0f;
            int cnt = 0;
            float fx = SXc(0), fy = SYc(0);
            float cx = fx, cy = fy;
            float sc = dx * (cy - aey) - dy * (cx - aex);
            float sf = sc;
            for (int i = 0; i < n; i++) {
                float nx, ny, sn;
                if (i + 1 == n) { nx = fx; ny = fy; sn = sf; }
                else {
                    nx = SXc(i + 1); ny = SYc(i + 1);
                    sn = dx * (ny - aey) - dy * (nx - aex);
                }
                bool ic = (sc >= 0.0f), in2 = (sn >= 0.0f);
                if (ic) {
                    if (cnt == 0) { fox = cx; foy = cy; }
                    else cr += pvx * cy - cx * pvy;
                    pvx = cx; pvy = cy; cnt++;
                }
                if (ic != in2) {
                    float t = sc / (sc - sn);
                    float ix = cx + t * (nx - cx);
                    float iy = cy + t * (ny - cy);
                    if (cnt == 0) { fox = ix; foy = iy; }
                    else cr += pvx * iy - ix * pvy;
                    pvx = ix; pvy = iy; cnt++;
                }
                cx = nx; cy = ny; sc = sn;
            }
            if (cnt) cr += pvx * foy - fox * pvy;
        }
        float inter = 0.5f * fabsf(cr);
        float uni = s_cwh[a2] + s_gwh[g] - inter;
        return inter / fmaxf(uni, 1e-9f);
    };

    // ---- phase A: this thread's 6 gts ----
    {
        float x0 = s_sq[0 * AB + al], y0 = s_sq[1 * AB + al];
        float x1 = s_sq[2 * AB + al], y1 = s_sq[3 * AB + al];
        float areaA = s_sq[4 * AB + al];
        unsigned mask = 0;
        unsigned long long bk = 0ull;
        #pragma unroll
        for (int j = 0; j < GPT; j++) {
            int g = part * GPT + j;
            if (!s_valid[g]) continue;
            unsigned long long k0 = (unsigned long long)(0xFFFFFFFFu - (unsigned)g);
            if (k0 > bk) bk = k0;
            float lx = fmaxf(x0, s_gx0[g]), ly = fmaxf(y0, s_gy0[g]);
            float rx = fminf(x1, s_gx1[g]), ry = fminf(y1, s_gy1[g]);
            float iw = fmaxf(rx - lx, 0.0f), ih = fmaxf(ry - ly, 0.0f);
            float inter0 = iw * ih;
            float ind = inter0 / fmaxf(areaA + s_areaG[g] - inter0, 1e-9f);
            if (ind >= 0.1f) mask |= (1u << g);
        }
        if (bk) atomicMax(&s_akey[al], bk);
        int np = __popc(mask);
        if (np) {
            int base = atomicAdd(&s_qn, np);
            while (mask) {
                int g = __ffs(mask) - 1;
                mask &= mask - 1;
                s_q[base++] = (unsigned short)((al << 5) | g);
            }
        }
    }
    __syncthreads();

    // ---- phase B: dense clips over queue (all 256 threads) ----
    int qn = s_qn;
    for (int i = tid; i < qn; i += TPB) {
        int a2 = s_q[i] >> 5, g = s_q[i] & 31;
        float iou = do_clip(a2, g);
        unsigned long long hb = ((unsigned long long)__float_as_uint(iou)) << 32;
        atomicMax(&s_akey[a2], hb | (unsigned long long)(0xFFFFFFFFu - (unsigned)g));
        atomicMax(&s_gtkey[g],
                  hb | (unsigned long long)(0xFFFFFFFFu -
                                            (unsigned)(blockIdx.x * AB + a2)));
    }
    __syncthreads();
    #undef SXc
    #undef SYc

    // ---- per-gt keys to global + block-local winner flags (24 threads) ----
    if (tid < GG) {
        unsigned long long kg = s_gtkey[tid];
        if (kg) atomicMax(&g_gtkey[b * GG + tid], kg);
        if (s_valid[tid]) {
            unsigned aw2 = 0xFFFFFFFFu - (unsigned)(kg & 0xFFFFFFFFull);
            int local = (int)aw2 - (int)(blockIdx.x * AB);
            if (local >= 0 && local < AB) s_winner[local] = 1;
        }
    }
    if (blockIdx.x == 0 && tid == 0) s_winner[0] = 1;  // seed-arg=0 safety
    // s_winner consumed only after the reduction barrier below

    // ---- phase C: per-anchor losses on primary threads ----
    float clssum = 0.0f, regsum = 0.0f, lmksum = 0.0f;
    bool pos = false, anyv = false;
    int ag = 0;
    float prr[CC];
    if (tid < AB) {
        unsigned long long k = s_akey[al];
        anyv = (s_anyv != 0);
        float iou_max;
        if (!anyv) { iou_max = -1.0f; ag = 0; }
        else {
            iou_max = __uint_as_float((unsigned)(k >> 32));
            ag = (int)(0xFFFFFFFFu - (unsigned)(k & 0xFFFFFFFFull));
        }
        pos = (iou_max >= 0.5f);

        prr[0] = pc0.x; prr[1] = pc0.y; prr[2] = pc0.z; prr[3] = pc0.w;
        prr[4] = pc1.x; prr[5] = pc1.y; prr[6] = pc1.z; prr[7] = pc1.w;
        if (pos || iou_max < 0.4f) {
            int lab = pos ? (int)s_gdat[ag][5] : -1;
            #pragma unroll
            for (int c = 0; c < CC; c++)
                clssum += (pos && c == lab) ? focal_pos(prr[c]) : focal_neg(prr[c]);
        }
        if (pos) {
            pos_losses_v(ax, ay, aw, ah, at, &s_gdat[ag][0], &s_lsd[ag][0],
                         pr0, pr1, pr2, pr3, pr4, pk.x, pk.y, pk.z, pk.w,
                         regsum, lmksum);
        }
    }

    // ---- block reduction ----
    {
        float c = clssum, r = regsum, l = lmksum, n = pos ? 1.0f : 0.0f;
        #pragma unroll
        for (int off = 16; off; off >>= 1) {
            c += __shfl_down_sync(0xFFFFFFFFu, c, off);
            r += __shfl_down_sync(0xFFFFFFFFu, r, off);
            l += __shfl_down_sync(0xFFFFFFFFu, l, off);
            n += __shfl_down_sync(0xFFFFFFFFu, n, off);
        }
        int warp = tid >> 5;
        if ((tid & 31) == 0) {
            s_wred[warp * 4 + 0] = c; s_wred[warp * 4 + 1] = r;
            s_wred[warp * 4 + 2] = l; s_wred[warp * 4 + 3] = n;
        }
        __syncthreads();   // also publishes s_winner
        if (tid < 4) {
            float acc = s_wred[tid];
            #pragma unroll
            for (int w = 1; w < 8; w++) acc += s_wred[w * 4 + tid];
            g_part[(b * NBLK + blockIdx.x) * 4 + tid] = acc;
        }
    }

    // ---- prospective deltas for block-local winners (flags, no scan) ----
    if (tid < AB && s_winner[al]) {
        float4 d = make_float4(0.0f, 0.0f, 0.0f, 0.0f);
        if (!pos && anyv) {
            int lab = (int)s_gdat[ag][5];
            float newc = 0.0f;
            #pragma unroll
            for (int c = 0; c < CC; c++)
                newc += (c == lab) ? focal_pos(prr[c]) : focal_neg(prr[c]);
            float dr, dl;
            pos_losses_v(ax, ay, aw, ah, at, &s_gdat[ag][0], &s_lsd[ag][0],
                         pr0, pr1, pr2, pr3, pr4, pk.x, pk.y, pk.z, pk.w,
                         dr, dl);
            d = make_float4(newc - clssum, dr, dl, 1.0f);
        }
        g_delta[idx] = d;
    }

    // ---- last-block election ----
    __threadfence();
    __syncthreads();
    if (tid == 0) {
        unsigned old = atomicInc(&g_done, NBLK_TOT - 1);
        s_last = (old == NBLK_TOT - 1);
    }
    __syncthreads();
    if (!s_last) return;
    __threadfence();

    // ================= fixer (warm last block, 256 threads) =================
    if (tid < BB * GG) {
        unsigned long long kk = g_gtkey[tid];
        if (kk < 0xFFFFFFFFull) kk = 0xFFFFFFFFull;  // seed (iou=0, a=0)
        f_key[tid] = kk;
        float lab = ann[tid * 6 + 5];
        f_lab[tid] = lab;
        float mx = __uint_as_float((unsigned)(kk >> 32));
        f_arg[tid] = (int)(0xFFFFFFFFu - (unsigned)(kk & 0xFFFFFFFFull));
        f_forced[tid] = (lab != -1.0f) && (mx < 0.5f);
    }
    __syncthreads();

    if (tid < BB * GG) {
        f_dc[tid] = 0.0f; f_dr[tid] = 0.0f; f_dl[tid] = 0.0f; f_dn[tid] = 0.0f;
        if (f_forced[tid]) {
            int bb2 = tid / GG;
            int a2 = f_arg[tid];
            bool unique = true;
            for (int t2 = bb2 * GG; t2 < tid; t2++)
                if (f_forced[t2] && f_arg[t2] == a2) unique = false;
            if (unique) {
                float4 d = g_delta[(long)bb2 * AA + a2];
                f_dc[tid] = d.x; f_dr[tid] = d.y; f_dl[tid] = d.z; f_dn[tid] = d.w;
            }
        }
    }

    // reduce 512 block partials: thread t sums 2 partials of its image
    {
        int bb2 = tid >> 7, kk = tid & 127;
        float4 p4a = ((const float4*)g_part)[bb2 * NBLK + kk];
        float4 p4b = ((const float4*)g_part)[bb2 * NBLK + 128 + kk];
        float c = p4a.x + p4b.x, r = p4a.y + p4b.y;
        float l = p4a.z + p4b.z, n = p4a.w + p4b.w;
        #pragma unroll
        for (int off = 16; off; off >>= 1) {
            c += __shfl_down_sync(0xFFFFFFFFu, c, off);
            r += __shfl_down_sync(0xFFFFFFFFu, r, off);
            l += __shfl_down_sync(0xFFFFFFFFu, l, off);
            n += __shfl_down_sync(0xFFFFFFFFu, n, off);
        }
        int warp = tid >> 5;
        if ((tid & 31) == 0) {
            f_w[warp * 4 + 0] = c; f_w[warp * 4 + 1] = r;
            f_w[warp * 4 + 2] = l; f_w[warp * 4 + 3] = n;
        }
    }
    __syncthreads();

    // per-image combine: warp 0 -> image 0, warp 1 -> image 1
    {
        int warp = tid >> 5, lane = tid & 31;
        if (warp < BB) {
            float cs = 0.0f, rs = 0.0f, lsum = 0.0f, npd = 0.0f;
            bool hg = false;
            if (lane < GG) {
                int t = warp * GG + lane;
                hg = (f_lab[t] != -1.0f);
                cs = f_dc[t]; rs = f_dr[t]; lsum = f_dl[t]; npd = f_dn[t];
            }
            unsigned bal = __ballot_sync(0xFFFFFFFFu, hg);
            #pragma unroll
            for (int off = 16; off; off >>= 1) {
                cs += __shfl_down_sync(0xFFFFFFFFu, cs, off);
                rs += __shfl_down_sync(0xFFFFFFFFu, rs, off);
                lsum += __shfl_down_sync(0xFFFFFFFFu, lsum, off);
                npd += __shfl_down_sync(0xFFFFFFFFu, npd, off);
            }
            if (lane == 0) {
                float np = npd;
                #pragma unroll
                for (int j = 0; j < 4; j++) {
                    cs += f_w[(warp * 4 + j) * 4 + 0];
                    rs += f_w[(warp * 4 + j) * 4 + 1];
                    lsum += f_w[(warp * 4 + j) * 4 + 2];
                    np += f_w[(warp * 4 + j) * 4 + 3];
                }
                bool has_gt = (bal != 0);
                float denom = fmaxf(np, 1.0f);
                float cm = 0.0f, rm = 0.0f, lm = 0.0f;
                if (has_gt) {
                    cm = cs / denom;
                    if (np > 0.0f) {
                        rm = rs / (5.0f * denom);
                        lm = lsum / (4.0f * denom);
                    }
                }
                f_img[warp][0] = cm; f_img[warp][1] = rm; f_img[warp][2] = lm;
            }
        }
    }
    __syncthreads();
    if (tid == 0) {
        out[0] = (f_img[0][0] + f_img[1][0]) / (float)BB;
        out[1] = (f_img[0][1] + f_img[1][1]) / (float)BB;
        out[2] = (f_img[0][2] + f_img[1][2]) / (float)BB;
    }
}

// ---------------- launch ----------------
extern "C" void kernel_launch(void* const* d_in, const int* in_sizes, int n_in,
                              void* d_out, int out_size) {
    const float* cls = (const float*)d_in[0];   // (B, A, C)
    const float* reg = (const float*)d_in[1];   // (B, A, 5)
    const float* anc = (const float*)d_in[2];   // (B, A, 5)
    const float* ann = (const float*)d_in[3];   // (B, G, 6)
    const float* lmk = (const float*)d_in[4];   // (B, A, 4)
    const float* ls  = (const float*)d_in[5];   // (B, G, 4)
    float* out = (float*)d_out;                 // 3 floats

    dim3 grid(NBLK, BB);
    k_main<<<grid, TPB>>>(anc, ann, cls, reg, lmk, ls, out);
}

// round 16
// speedup vs baseline: 1.3674x; 1.3674x over previous
#include <cuda_runtime.h>
#include <math.h>

// Problem shapes (fixed for MultiLoss_87668872446687)
#define BB 2
#define AA 16384
#define GG 24
#define CC 8
#define TPB 256
#define AB 64                       // anchors per block (4 threads per anchor)
#define GPT 6                       // gts per thread (24/4)
#define NBLK (AA / AB)              // 256 blocks per image
#define NBLK_TOT (BB * NBLK)        // 512
#define QCAP (AB * GG)              // 1536 = hard maximum

// ---------------- scratch (device globals; no allocations) ----------------
__device__ unsigned long long g_gtkey[BB * GG];
__device__ float  g_part[NBLK_TOT * 4];
__device__ float4 g_delta[BB * AA];
__device__ unsigned g_done;

// ---------------- helpers ----------------
__device__ __forceinline__ float smooth_l1(float d) {
    const float beta = 1.0f / 9.0f;
    d = fabsf(d);
    return (d < beta) ? (0.5f * d * d / beta) : (d - 0.5f * beta);
}

__device__ __forceinline__ float balanced_l1(float d) {
    const float bb = 5.0496474644129465f;  // e^(0.9/0.5) - 1
    const float al = 0.5f, ga = 0.9f, beta = 0.5f;
    d = fabsf(d);
    if (d < beta)
        return al / bb * (bb * d + 1.0f) * __logf(bb * d / beta + 1.0f) - al * d;
    return ga * d + ga / bb - al * beta;
}

__device__ __forceinline__ float focal_neg(float p) {
    p = fminf(fmaxf(p, 1e-4f), 1.0f - 1e-4f);
    return 0.75f * p * p * (-__logf(1.0f - p + 1e-6f));
}
__device__ __forceinline__ float focal_pos(float p) {
    p = fminf(fmaxf(p, 1e-4f), 1.0f - 1e-4f);
    float q = 1.0f - p;
    return 0.25f * q * q * (-__logf(p + 1e-6f));
}

__device__ __forceinline__ void pos_losses(
        float acx, float acy, float aw, float ah, float ath,
        const float* gp, const float* lp,
        const float* rp, const float* kp,
        float& regsum, float& lmksum) {
    float ew = fmaxf(aw, 1.0f), eh = fmaxf(ah, 1.0f);
    float gw = fmaxf(gp[2], 1.0f), gh = fmaxf(gp[3], 1.0f);
    float ta = __tanf(ath);
    float dx = 10.0f * (gp[0] - acx) / ew;
    float dy = 10.0f * (gp[1] - acy) / eh;
    float dw = 5.0f * __logf(gw / ew);
    float dh = 5.0f * __logf(gh / eh);
    float dt = 15.0f * (__tanf(gp[4]) - ta);

    float r0 = rp[0], r1 = rp[1], r2 = rp[2], r3 = rp[3], r4 = rp[4];

    float tg = r4 / 15.0f + ta;
    if (fabsf(tg) < 1e-4f) tg = (tg < 0.0f) ? -1e-4f : 1e-4f;
    float t22 = 15.0f * (-1.0f / tg - ta);

    float l1 = smooth_l1(dx - r0), l2 = smooth_l1(dy - r1);
    float l3 = smooth_l1(dw - r2), l4 = smooth_l1(dh - r3);
    float l5 = smooth_l1(dw - r3), l6 = smooth_l1(dh - r2);
    float l7 = smooth_l1(dt - r4), l8 = smooth_l1(dt - t22);
    regsum = fminf(l1 + l2 + l3 + l4 + l7, l1 + l2 + l5 + l6 + l8);

    float t0 = 10.0f * (lp[0] - acx) / ew;
    float t1_ = 10.0f * (lp[1] - acy) / eh;
    float t2 = 10.0f * (lp[2] - acx) / ew;
    float t3 = 10.0f * (lp[3] - acy) / eh;
    lmksum = balanced_l1(kp[0] - t0) + balanced_l1(kp[1] - t1_) +
             balanced_l1(kp[2] - t2) + balanced_l1(kp[3] - t3);
}

// ---------------- fused kernel ----------------
__global__ void __launch_bounds__(TPB, 4) k_main(
        const float* __restrict__ anchors,
        const float* __restrict__ ann,
        const float* __restrict__ cls,
        const float* __restrict__ reg,
        const float* __restrict__ lmk,
        const float* __restrict__ ls,
        float* __restrict__ out) {
    // gt caches
    __shared__ float s_gx0[GG], s_gy0[GG], s_gx1[GG], s_gy1[GG], s_areaG[GG];
    __shared__ float s_gax[GG][4], s_gay[GG][4];
    __shared__ float s_gdx[GG][4], s_gdy[GG][4];
    __shared__ float s_gwh[GG];
    __shared__ float s_gdat[GG][6];
    __shared__ float s_lsd[GG][4];
    __shared__ int   s_valid[GG];
    __shared__ int   s_anyv;
    __shared__ unsigned long long s_gtkey[GG];
    // per-anchor (AB = 64)
    __shared__ unsigned long long s_akey[AB];
    __shared__ float s_corn[8 * AB];
    __shared__ float s_cwh[AB];
    __shared__ float s_sq[5 * AB];
    __shared__ int   s_winner[AB];
    // pair queue
    __shared__ unsigned short s_q[QCAP];
    __shared__ int s_qn;
    __shared__ int s_last;
    // clip scratch: buffer A = slots 0..6, buffer B = slots 7..12
    __shared__ float s_clip[26 * TPB];
    __shared__ float s_wred[8 * 4];
    // fixer state
    __shared__ unsigned long long f_key[BB * GG];
    __shared__ float f_lab[BB * GG];
    __shared__ float f_dc[BB * GG], f_dr[BB * GG], f_dl[BB * GG], f_dn[BB * GG];
    __shared__ int   f_arg[BB * GG], f_forced[BB * GG];
    __shared__ float f_w[8 * 4];
    __shared__ float f_img[BB][3];

    const int b = blockIdx.y;
    const int tid = threadIdx.x;
    const int al = tid & (AB - 1);       // anchor within block
    const int part = tid >> 6;           // 0..3: which 6 gts this thread covers
    const int a = blockIdx.x * AB + al;  // global anchor within image
    const long idx = (long)b * AA + a;

    if (tid == 0) s_qn = 0;
    if (tid < AB) s_winner[al] = 0;
    if (tid < GG) {
        const float* gp = ann + (b * GG + tid) * 6;
        float gx = gp[0], gy = gp[1], gw = gp[2], gh = gp[3], gt = gp[4];
        s_gdat[tid][0] = gx; s_gdat[tid][1] = gy; s_gdat[tid][2] = gw;
        s_gdat[tid][3] = gh; s_gdat[tid][4] = gt; s_gdat[tid][5] = gp[5];
        s_valid[tid] = (gp[5] != -1.0f);
        s_gwh[tid] = gw * gh;
        float gs2 = 0.5f * fmaxf(gw, gh);
        float x0 = gx - gs2, y0 = gy - gs2, x1 = gx + gs2, y1 = gy + gs2;
        s_gx0[tid] = x0; s_gy0[tid] = y0; s_gx1[tid] = x1; s_gy1[tid] = y1;
        s_areaG[tid] = (x1 - x0) * (y1 - y0);
        float c = cosf(gt), s = sinf(gt);
        float hw = 0.5f * gw, hh = 0.5f * gh;
        float cx0 = gx - hw * c + hh * s, cy0 = gy - hw * s - hh * c;
        float cx1 = gx + hw * c + hh * s, cy1 = gy + hw * s - hh * c;
        float cx2 = gx + hw * c - hh * s, cy2 = gy + hw * s + hh * c;
        float cx3 = gx - hw * c - hh * s, cy3 = gy - hw * s + hh * c;
        s_gax[tid][0] = cx0; s_gay[tid][0] = cy0;
        s_gdx[tid][0] = cx1 - cx0; s_gdy[tid][0] = cy1 - cy0;
        s_gax[tid][1] = cx1; s_gay[tid][1] = cy1;
        s_gdx[tid][1] = cx2 - cx1; s_gdy[tid][1] = cy2 - cy1;
        s_gax[tid][2] = cx2; s_gay[tid][2] = cy2;
        s_gdx[tid][2] = cx3 - cx2; s_gdy[tid][2] = cy3 - cy2;
        s_gax[tid][3] = cx3; s_gay[tid][3] = cy3;
        s_gdx[tid][3] = cx0 - cx3; s_gdy[tid][3] = cy0 - cy3;
        s_gtkey[tid] = 0ull;
        const float* lq = ls + (b * GG + tid) * 4;
        s_lsd[tid][0] = lq[0]; s_lsd[tid][1] = lq[1];
        s_lsd[tid][2] = lq[2]; s_lsd[tid][3] = lq[3];
    }

    // primary thread per anchor; prefetch cls early (consumed in phase C)
    float ax = 0, ay = 0, aw = 0, ah = 0, at = 0;
    float4 pc0 = make_float4(0.f, 0.f, 0.f, 0.f);
    float4 pc1 = make_float4(0.f, 0.f, 0.f, 0.f);
    if (tid < AB) {
        const float4* cv = (const float4*)(cls + idx * CC);
        pc0 = cv[0]; pc1 = cv[1];
        const float* apt = anchors + idx * 5;
        ax = apt[0]; ay = apt[1]; aw = apt[2]; ah = apt[3]; at = apt[4];
        float c = cosf(at), s = sinf(at);
        float hw = 0.5f * aw, hh = 0.5f * ah;
        s_corn[0 * AB + al] = ax - hw * c + hh * s;
        s_corn[1 * AB + al] = ay - hw * s - hh * c;
        s_corn[2 * AB + al] = ax + hw * c + hh * s;
        s_corn[3 * AB + al] = ay + hw * s - hh * c;
        s_corn[4 * AB + al] = ax + hw * c - hh * s;
        s_corn[5 * AB + al] = ay + hw * s + hh * c;
        s_corn[6 * AB + al] = ax - hw * c - hh * s;
        s_corn[7 * AB + al] = ay - hw * s + hh * c;
        s_cwh[al] = aw * ah;
        float as2 = 0.5f * fmaxf(aw, ah);
        float x0 = ax - as2, y0 = ay - as2, x1 = ax + as2, y1 = ay + as2;
        s_sq[0 * AB + al] = x0; s_sq[1 * AB + al] = y0;
        s_sq[2 * AB + al] = x1; s_sq[3 * AB + al] = y1;
        s_sq[4 * AB + al] = (x1 - x0) * (y1 - y0);
        s_akey[al] = 0ull;
    }
    __syncthreads();

    if (tid == 0) {
        int v = 0;
        #pragma unroll
        for (int g = 0; g < GG; g++) v |= s_valid[g];
        s_anyv = v;
    }

    // clip: buffers A (slots 0..6), B (slots 7..12); edge3 fused with area
    #define SXc(i) s_clip[(i) * TPB + tid]
    #define SYc(i) s_clip[(13 + (i)) * TPB + tid]
    auto do_clip = [&](int a2, int g) -> float {
        float v0x = s_corn[0 * AB + a2], v0y = s_corn[1 * AB + a2];
        float v1x = s_corn[2 * AB + a2], v1y = s_corn[3 * AB + a2];
        float v2x = s_corn[4 * AB + a2], v2y = s_corn[5 * AB + a2];
        float v3x = s_corn[6 * AB + a2], v3y = s_corn[7 * AB + a2];

        // edge 0: input = rect corners (registers) -> buffer A
        float aex = s_gax[g][0], aey = s_gay[g][0];
        float dx = s_gdx[g][0], dy = s_gdy[g][0];
        float sc0 = dx * (v0y - aey) - dy * (v0x - aex);
        float sc1 = dx * (v1y - aey) - dy * (v1x - aex);
        float sc2 = dx * (v2y - aey) - dy * (v2x - aex);
        float sc3 = dx * (v3y - aey) - dy * (v3x - aex);
        int m = 0;
        #define EMIT0(cx, cy, nx, ny, sc, sn)                          \
            do {                                                       \
                bool ic = ((sc) >= 0.0f), in2 = ((sn) >= 0.0f);        \
                if (ic) { SXc(m) = (cx); SYc(m) = (cy); m++; }         \
                if (ic != in2) {                                       \
                    float t = (sc) / ((sc) - (sn));                    \
                    SXc(m) = (cx) + t * ((nx) - (cx));                 \
                    SYc(m) = (cy) + t * ((ny) - (cy));                 \
                    m++;                                               \
                }                                                      \
            } while (0)
        EMIT0(v0x, v0y, v1x, v1y, sc0, sc1);
        EMIT0(v1x, v1y, v2x, v2y, sc1, sc2);
        EMIT0(v2x, v2y, v3x, v3y, sc2, sc3);
        EMIT0(v3x, v3y, v0x, v0y, sc3, sc0);
        #undef EMIT0

        int n = m;
        // edges 1 (A->B) and 2 (B->A)
        #pragma unroll
        for (int e = 1; e <= 2; e++) {
            if (n == 0) break;
            int rb = (e == 1) ? 0 : 7;
            int wb = (e == 1) ? 7 : 0;
            aex = s_gax[g][e]; aey = s_gay[g][e];
            dx = s_gdx[g][e];  dy = s_gdy[g][e];
            m = 0;
            float fx = SXc(rb), fy = SYc(rb);
            float cx = fx, cy = fy;
            float sc = dx * (cy - aey) - dy * (cx - aex);
            float sf = sc;
            for (int i = 0; i < n; i++) {
                float nx, ny, sn;
                if (i + 1 == n) { nx = fx; ny = fy; sn = sf; }
                else {
                    nx = SXc(rb + i + 1); ny = SYc(rb + i + 1);
                    sn = dx * (ny - aey) - dy * (nx - aex);
                }
                bool ic = (sc >= 0.0f), in2 = (sn >= 0.0f);
                if (ic) { SXc(wb + m) = cx; SYc(wb + m) = cy; m++; }
                if (ic != in2) {
                    float t = sc / (sc - sn);
                    SXc(wb + m) = cx + t * (nx - cx);
                    SYc(wb + m) = cy + t * (ny - cy);
                    m++;
                }
                cx = nx; cy = ny; sc = sn;
            }
            n = m;
        }

        // edge 3 (reads A) fused with shoelace area (bit-identical order)
        float cr = 0.0f;
        if (n) {
            aex = s_gax[g][3]; aey = s_gay[g][3];
            dx = s_gdx[g][3];  dy = s_gdy[g][3];
            float fox = 0.0f, foy = 0.0f, pvx = 0.0f, pvy = 0.0f;
            int cnt = 0;
            float fx = SXc(0), fy = SYc(0);
            float cx = fx, cy = fy;
            float sc = dx * (cy - aey) - dy * (cx - aex);
            float sf = sc;
            for (int i = 0; i < n; i++) {
                float nx, ny, sn;
                if (i + 1 == n) { nx = fx; ny = fy; sn = sf; }
                else {
                    nx = SXc(i + 1); ny = SYc(i + 1);
                    sn = dx * (ny - aey) - dy * (nx - aex);
                }
                bool ic = (sc >= 0.0f), in2 = (sn >= 0.0f);
                if (ic) {
                    if (cnt == 0) { fox = cx; foy = cy; }
                    else cr += pvx * cy - cx * pvy;
                    pvx = cx; pvy = cy; cnt++;
                }
                if (ic != in2) {
                    float t = sc / (sc - sn);
                    float ix = cx + t * (nx - cx);
                    float iy = cy + t * (ny - cy);
                    if (cnt == 0) { fox = ix; foy = iy; }
                    else cr += pvx * iy - ix * pvy;
                    pvx = ix; pvy = iy; cnt++;
                }
                cx = nx; cy = ny; sc = sn;
            }
            if (cnt) cr += pvx * foy - fox * pvy;
        }
        float inter = 0.5f * fabsf(cr);
        float uni = s_cwh[a2] + s_gwh[g] - inter;
        return inter / fmaxf(uni, 1e-9f);
    };

    // ---- phase A: this thread's 6 gts ----
    {
        float x0 = s_sq[0 * AB + al], y0 = s_sq[1 * AB + al];
        float x1 = s_sq[2 * AB + al], y1 = s_sq[3 * AB + al];
        float areaA = s_sq[4 * AB + al];
        unsigned mask = 0;
        unsigned long long bk = 0ull;
        #pragma unroll
        for (int j = 0; j < GPT; j++) {
            int g = part * GPT + j;
            if (!s_valid[g]) continue;
            unsigned long long k0 = (unsigned long long)(0xFFFFFFFFu - (unsigned)g);
            if (k0 > bk) bk = k0;
            float lx = fmaxf(x0, s_gx0[g]), ly = fmaxf(y0, s_gy0[g]);
            float rx = fminf(x1, s_gx1[g]), ry = fminf(y1, s_gy1[g]);
            float iw = fmaxf(rx - lx, 0.0f), ih = fmaxf(ry - ly, 0.0f);
            float inter0 = iw * ih;
            float ind = inter0 / fmaxf(areaA + s_areaG[g] - inter0, 1e-9f);
            if (ind >= 0.1f) mask |= (1u << g);
        }
        if (bk) atomicMax(&s_akey[al], bk);
        int np = __popc(mask);
        if (np) {
            int base = atomicAdd(&s_qn, np);
            while (mask) {
                int g = __ffs(mask) - 1;
                mask &= mask - 1;
                s_q[base++] = (unsigned short)((al << 5) | g);
            }
        }
    }
    __syncthreads();

    // ---- phase B: dense clips over queue (all 256 threads) ----
    int qn = s_qn;
    for (int i = tid; i < qn; i += TPB) {
        int a2 = s_q[i] >> 5, g = s_q[i] & 31;
        float iou = do_clip(a2, g);
        unsigned long long hb = ((unsigned long long)__float_as_uint(iou)) << 32;
        atomicMax(&s_akey[a2], hb | (unsigned long long)(0xFFFFFFFFu - (unsigned)g));
        atomicMax(&s_gtkey[g],
                  hb | (unsigned long long)(0xFFFFFFFFu -
                                            (unsigned)(blockIdx.x * AB + a2)));
    }
    __syncthreads();
    #undef SXc
    #undef SYc

    // ---- per-gt keys to global + block-local winner flags (24 threads) ----
    if (tid < GG) {
        unsigned long long kg = s_gtkey[tid];
        if (kg) atomicMax(&g_gtkey[b * GG + tid], kg);
        if (s_valid[tid]) {
            unsigned aw2 = 0xFFFFFFFFu - (unsigned)(kg & 0xFFFFFFFFull);
            int local = (int)aw2 - (int)(blockIdx.x * AB);
            if (local >= 0 && local < AB) s_winner[local] = 1;
        }
    }
    if (blockIdx.x == 0 && tid == 0) s_winner[0] = 1;  // seed-arg=0 safety
    __syncthreads();  // publish s_winner before phase C

    // ---- phase C: per-anchor losses on primary threads ----
    float clssum = 0.0f, regsum = 0.0f, lmksum = 0.0f;
    bool pos = false;
    if (tid < AB) {
        unsigned long long k = s_akey[al];
        bool anyv = (s_anyv != 0);
        float iou_max; int ag;
        if (!anyv) { iou_max = -1.0f; ag = 0; }
        else {
            iou_max = __uint_as_float((unsigned)(k >> 32));
            ag = (int)(0xFFFFFFFFu - (unsigned)(k & 0xFFFFFFFFull));
        }
        pos = (iou_max >= 0.5f);

        float pr[CC] = {pc0.x, pc0.y, pc0.z, pc0.w, pc1.x, pc1.y, pc1.z, pc1.w};
        if (pos || iou_max < 0.4f) {
            int lab = pos ? (int)s_gdat[ag][5] : -1;
            #pragma unroll
            for (int c = 0; c < CC; c++)
                clssum += (pos && c == lab) ? focal_pos(pr[c]) : focal_neg(pr[c]);
        }
        if (pos) {
            pos_losses(ax, ay, aw, ah, at, &s_gdat[ag][0], &s_lsd[ag][0],
                       reg + idx * 5, lmk + idx * 4, regsum, lmksum);
        }

        // prospective deltas for block-local winners (flag, no key scan)
        if (s_winner[al]) {
            float4 d = make_float4(0.0f, 0.0f, 0.0f, 0.0f);
            if (!pos && anyv) {
                int lab = (int)s_gdat[ag][5];
                float newc = 0.0f;
                #pragma unroll
                for (int c = 0; c < CC; c++)
                    newc += (c == lab) ? focal_pos(pr[c]) : focal_neg(pr[c]);
                float dr, dl;
                pos_losses(ax, ay, aw, ah, at, &s_gdat[ag][0], &s_lsd[ag][0],
                           reg + idx * 5, lmk + idx * 4, dr, dl);
                d = make_float4(newc - clssum, dr, dl, 1.0f);
            }
            g_delta[idx] = d;
        }
    }

    // ---- block reduction ----
    {
        float c = clssum, r = regsum, l = lmksum, n = pos ? 1.0f : 0.0f;
        #pragma unroll
        for (int off = 16; off; off >>= 1) {
            c += __shfl_down_sync(0xFFFFFFFFu, c, off);
            r += __shfl_down_sync(0xFFFFFFFFu, r, off);
            l += __shfl_down_sync(0xFFFFFFFFu, l, off);
            n += __shfl_down_sync(0xFFFFFFFFu, n, off);
        }
        int warp = tid >> 5;
        if ((tid & 31) == 0) {
            s_wred[warp * 4 + 0] = c; s_wred[warp * 4 + 1] = r;
            s_wred[warp * 4 + 2] = l; s_wred[warp * 4 + 3] = n;
        }
        __syncthreads();
        if (tid < 4) {
            float acc = s_wred[tid];
            #pragma unroll
            for (int w = 1; w < 8; w++) acc += s_wred[w * 4 + tid];
            g_part[(b * NBLK + blockIdx.x) * 4 + tid] = acc;
        }
    }

    // ---- last-block election ----
    __threadfence();
    __syncthreads();
    if (tid == 0) {
        unsigned old = atomicInc(&g_done, NBLK_TOT - 1);
        s_last = (old == NBLK_TOT - 1);
    }
    __syncthreads();
    if (!s_last) return;
    __threadfence();

    // ================= fixer (warm last block, 256 threads) =================
    if (tid < BB * GG) {
        unsigned long long kk = g_gtkey[tid];
        if (kk < 0xFFFFFFFFull) kk = 0xFFFFFFFFull;  // seed (iou=0, a=0)
        f_key[tid] = kk;
        float lab = ann[tid * 6 + 5];
        f_lab[tid] = lab;
        float mx = __uint_as_float((unsigned)(kk >> 32));
        f_arg[tid] = (int)(0xFFFFFFFFu - (unsigned)(kk & 0xFFFFFFFFull));
        f_forced[tid] = (lab != -1.0f) && (mx < 0.5f);
    }
    __syncthreads();

    if (tid < BB * GG) {
        f_dc[tid] = 0.0f; f_dr[tid] = 0.0f; f_dl[tid] = 0.0f; f_dn[tid] = 0.0f;
        if (f_forced[tid]) {
            int bb2 = tid / GG;
            int a2 = f_arg[tid];
            bool unique = true;
            for (int t2 = bb2 * GG; t2 < tid; t2++)
                if (f_forced[t2] && f_arg[t2] == a2) unique = false;
            if (unique) {
                float4 d = g_delta[(long)bb2 * AA + a2];
                f_dc[tid] = d.x; f_dr[tid] = d.y; f_dl[tid] = d.z; f_dn[tid] = d.w;
            }
        }
    }

    // reduce 512 block partials: thread t sums 2 partials of its image
    {
        int bb2 = tid >> 7, kk = tid & 127;
        float4 p4a = ((const float4*)g_part)[bb2 * NBLK + kk];
        float4 p4b = ((const float4*)g_part)[bb2 * NBLK + 128 + kk];
        float c = p4a.x + p4b.x, r = p4a.y + p4b.y;
        float l = p4a.z + p4b.z, n = p4a.w + p4b.w;
        #pragma unroll
        for (int off = 16; off; off >>= 1) {
            c += __shfl_down_sync(0xFFFFFFFFu, c, off);
            r += __shfl_down_sync(0xFFFFFFFFu, r, off);
            l += __shfl_down_sync(0xFFFFFFFFu, l, off);
            n += __shfl_down_sync(0xFFFFFFFFu, n, off);
        }
        int warp = tid >> 5;
        if ((tid & 31) == 0) {
            f_w[warp * 4 + 0] = c; f_w[warp * 4 + 1] = r;
            f_w[warp * 4 + 2] = l; f_w[warp * 4 + 3] = n;
        }
    }
    __syncthreads();

    // per-image combine: warp 0 -> image 0, warp 1 -> image 1
    {
        int warp = tid >> 5, lane = tid & 31;
        if (warp < BB) {
            float cs = 0.0f, rs = 0.0f, lsum = 0.0f, npd = 0.0f;
            bool hg = false;
            if (lane < GG) {
                int t = warp * GG + lane;
                hg = (f_lab[t] != -1.0f);
                cs = f_dc[t]; rs = f_dr[t]; lsum = f_dl[t]; npd = f_dn[t];
            }
            unsigned bal = __ballot_sync(0xFFFFFFFFu, hg);
            #pragma unroll
            for (int off = 16; off; off >>= 1) {
                cs += __shfl_down_sync(0xFFFFFFFFu, cs, off);
                rs += __shfl_down_sync(0xFFFFFFFFu, rs, off);
                lsum += __shfl_down_sync(0xFFFFFFFFu, lsum, off);
                npd += __shfl_down_sync(0xFFFFFFFFu, npd, off);
            }
            if (lane == 0) {
                float np = npd;
                #pragma unroll
                for (int j = 0; j < 4; j++) {
                    cs += f_w[(warp * 4 + j) * 4 + 0];
                    rs += f_w[(warp * 4 + j) * 4 + 1];
                    lsum += f_w[(warp * 4 + j) * 4 + 2];
                    np += f_w[(warp * 4 + j) * 4 + 3];
                }
                bool has_gt = (bal != 0);
                float denom = fmaxf(np, 1.0f);
                float cm = 0.0f, rm = 0.0f, lm = 0.0f;
                if (has_gt) {
                    cm = cs / denom;
                    if (np > 0.0f) {
                        rm = rs / (5.0f * denom);
                        lm = lsum / (4.0f * denom);
                    }
                }
                f_img[warp][0] = cm; f_img[warp][1] = rm; f_img[warp][2] = lm;
            }
        }
    }
    __syncthreads();
    if (tid == 0) {
        out[0] = (f_img[0][0] + f_img[1][0]) / (float)BB;
        out[1] = (f_img[0][1] + f_img[1][1]) / (float)BB;
        out[2] = (f_img[0][2] + f_img[1][2]) / (float)BB;
    }
}

// ---------------- launch ----------------
extern "C" void kernel_launch(void* const* d_in, const int* in_sizes, int n_in,
                              void* d_out, int out_size) {
    const float* cls = (const float*)d_in[0];   // (B, A, C)
    const float* reg = (const float*)d_in[1];   // (B, A, 5)
    const float* anc = (const float*)d_in[2];   // (B, A, 5)
    const float* ann = (const float*)d_in[3];   // (B, G, 6)
    const float* lmk = (const float*)d_in[4];   // (B, A, 4)
    const float* ls  = (const float*)d_in[5];   // (B, G, 4)
    float* out = (float*)d_out;                 // 3 floats

    dim3 grid(NBLK, BB);
    k_main<<<grid, TPB>>>(anc, ann, cls, reg, lmk, ls, out);
}